// round 6
// baseline (speedup 1.0000x reference)
#include <cuda_runtime.h>
#include <cstdint>

#define NC 1024
#define DY 16
#define G  256
#define M  2
#define CH 64
#define NT 16          // tiles per dim (G/16)
#define S  4           // split-K segments per tile
#define ZTOT (M * G * G * 17)     // 2,228,224 z elements
#define XTOT (M * G * G * 2)      // 262,144 x_grid elements

typedef unsigned long long u64;

// Axis-separable weight matrices: g_W[axis][m][grid_idx][c]
__device__ float g_W[2][M][G][NC];           // 4 MB
__device__ int   g_len[M][NT][NT];
__device__ int   g_list[M][NT][NT][NC];      // 2 MB
__device__ float g_part[S][ZTOT];            // 35.6 MB split-K partials

// ---- packed f32x2 helpers (sm_103a) ----
__device__ __forceinline__ u64 pack2(float lo, float hi) {
    u64 r; asm("mov.b64 %0, {%1, %2};" : "=l"(r) : "f"(lo), "f"(hi)); return r;
}
__device__ __forceinline__ void unpack2(float& lo, float& hi, u64 v) {
    asm("mov.b64 {%0, %1}, %2;" : "=f"(lo), "=f"(hi) : "l"(v));
}
__device__ __forceinline__ void ffma2(u64& d, u64 a, u64 b) {
    asm("fma.rn.f32x2 %0, %1, %2, %0;" : "+l"(d) : "l"(a), "l"(b));
}
__device__ __forceinline__ void lds_v2_u64(u64& a, u64& b, uint32_t addr) {
    asm volatile("ld.shared.v2.b64 {%0, %1}, [%2];" : "=l"(a), "=l"(b) : "r"(addr));
}

// ---------------------------------------------------------------------------
// Kernel 1: build Wx/Wy (1M exps, MUFU path)
// ---------------------------------------------------------------------------
__global__ void weights_kernel(const float* __restrict__ xc,
                               const float* __restrict__ lsp) {
    int idx = blockIdx.x * blockDim.x + threadIdx.x;   // 1,048,576
    int c = idx & (NC - 1);
    int i = (idx >> 10) & (G - 1);
    int d = (idx >> 18) & 1;
    int m = idx >> 19;
    float l = 1e-5f + log1pf(expf(lsp[d]));            // exact softplus (once)
    float rl = 1.0f / l;
    float g = 1.0f + (float)(i - 128) * (1.0f / 64.0f);
    float x = xc[(m * NC + c) * 2 + d];
    float t = (g - x) * rl;
    g_W[d][m][i][c] = __expf(-0.5f * t * t);
}

// ---------------------------------------------------------------------------
// Kernel 2: per-tile c-list compaction (one warp per tile, deterministic)
// ---------------------------------------------------------------------------
__global__ void compact_kernel(const float* __restrict__ xc,
                               const float* __restrict__ lsp) {
    int warp = (blockIdx.x * blockDim.x + threadIdx.x) >> 5;
    int lane = threadIdx.x & 31;
    if (warp >= M * NT * NT) return;
    int jT = warp & (NT - 1);
    int iT = (warp >> 4) & (NT - 1);
    int m  = warp >> 8;

    float rlx = 1.0f / (1e-5f + log1pf(expf(lsp[0])));
    float rly = 1.0f / (1e-5f + log1pf(expf(lsp[1])));
    float x0 = 1.0f + (float)(iT * 16 - 128) * (1.0f / 64.0f);
    float x1 = x0 + 15.0f / 64.0f;
    float y0 = 1.0f + (float)(jT * 16 - 128) * (1.0f / 64.0f);
    float y1 = y0 + 15.0f / 64.0f;
    const float thr = 27.63f;   // weight cutoff ~1e-6

    int count = 0;
    int* lst = g_list[m][iT][jT];
    for (int c0 = 0; c0 < NC; c0 += 32) {
        int c = c0 + lane;
        float cx = xc[(m * NC + c) * 2 + 0];
        float cy = xc[(m * NC + c) * 2 + 1];
        float dx = fmaxf(fmaxf(x0 - cx, cx - x1), 0.0f) * rlx;
        float dy = fmaxf(fmaxf(y0 - cy, cy - y1), 0.0f) * rly;
        bool keep = (dx * dx + dy * dy) <= thr;
        unsigned mask = __ballot_sync(0xffffffffu, keep);
        int off = __popc(mask & ((1u << lane) - 1u));
        if (keep) lst[count + off] = c;
        count += __popc(mask);
    }
    if (lane == 0) g_len[m][iT][jT] = count;
}

// ---------------------------------------------------------------------------
// Kernel 3: split-K partial contraction. grid = (NT, NT, M*S).
// Segment s of tile (m,iT,jT) handles list entries [s*seg, min((s+1)*seg,len)).
// ---------------------------------------------------------------------------
__global__ __launch_bounds__(256)
void setconv_partial(const float* __restrict__ yc) {
    __shared__ float  wxs[CH][17];
    __shared__ float  wys[CH][17];
    __shared__ float4 ycs[CH][4];

    const int zid = blockIdx.z;
    const int m  = zid >> 2;
    const int s  = zid & (S - 1);
    const int iT = blockIdx.y;
    const int jT = blockIdx.x;
    const int tid = threadIdx.x;
    const int ti = tid >> 4;
    const int tj = tid & 15;
    const int iBase = iT * 16;
    const int jBase = jT * 16;

    u64 acc2[8];
#pragma unroll
    for (int q = 0; q < 8; q++) acc2[q] = 0ull;
    float accD = 0.0f;

    const int len = g_len[m][iT][jT];
    const int seg = (len + S - 1) >> 2;
    const int lo  = s * seg;
    const int hi  = min(lo + seg, len);
    const int* __restrict__ lst = g_list[m][iT][jT];
    const float4* __restrict__ yc4 = (const float4*)yc;
    const uint32_t ycs_addr = (uint32_t)__cvta_generic_to_shared(&ycs[0][0]);

    for (int c0 = lo; c0 < hi; c0 += CH) {
        // --- stage chunk (gathered via list) ---
#pragma unroll
        for (int r = 0; r < 4; r++) {
            int idx = tid + r * 256;
            int cc = idx & (CH - 1);
            int ii = idx >> 6;
            int cpos = c0 + cc;
            bool valid = cpos < hi;
            int cidx = valid ? lst[cpos] : 0;
            wxs[cc][ii] = valid ? g_W[0][m][iBase + ii][cidx] : 0.0f;
            wys[cc][ii] = valid ? g_W[1][m][jBase + ii][cidx] : 0.0f;
        }
        {
            int cc = tid >> 2, q = tid & 3;
            int cpos = c0 + cc;
            int cidx = (cpos < hi) ? lst[cpos] : 0;
            ycs[cc][q] = yc4[((m * NC + cidx) << 2) + q];
        }
        __syncthreads();

        // --- accumulate (packed f32x2) ---
#pragma unroll 4
        for (int cc = 0; cc < CH; ++cc) {
            float w = wxs[cc][ti] * wys[cc][tj];
            accD += w;
            u64 w2 = pack2(w, w);
            u64 y0, y1, y2, y3, y4, y5, y6, y7;
            uint32_t a = ycs_addr + cc * 64;
            lds_v2_u64(y0, y1, a);
            lds_v2_u64(y2, y3, a + 16);
            lds_v2_u64(y4, y5, a + 32);
            lds_v2_u64(y6, y7, a + 48);
            ffma2(acc2[0], w2, y0);
            ffma2(acc2[1], w2, y1);
            ffma2(acc2[2], w2, y2);
            ffma2(acc2[3], w2, y3);
            ffma2(acc2[4], w2, y4);
            ffma2(acc2[5], w2, y5);
            ffma2(acc2[6], w2, y6);
            ffma2(acc2[7], w2, y7);
        }
        __syncthreads();
    }

    // --- write partials ---
    float acc[DY];
#pragma unroll
    for (int q = 0; q < 8; q++) unpack2(acc[2 * q], acc[2 * q + 1], acc2[q]);

    const int i = iBase + ti, j = jBase + tj;
    float* po = &g_part[s][((size_t)((m * G + i) * G + j)) * 17];
#pragma unroll
    for (int k = 0; k < DY; k++) po[k] = acc[k];
    po[16] = accD;
}

// ---------------------------------------------------------------------------
// Kernel 4: finalize — one thread per output element.
//   idx < XTOT: x_grid_b coordinates; else: deterministic fixed-order
//   sum of the S split-K partials.
// ---------------------------------------------------------------------------
__global__ void finalize_kernel(float* __restrict__ out) {
    int idx = blockIdx.x * blockDim.x + threadIdx.x;   // 2,490,368 total
    if (idx < XTOT) {
        int d = idx & 1;
        int j = (idx >> 1) & (G - 1);
        int i = (idx >> 9) & (G - 1);
        int v = d ? j : i;
        out[idx] = 1.0f + (float)(v - 128) * (1.0f / 64.0f);
    } else {
        int e = idx - XTOT;
        float v = ((g_part[0][e] + g_part[1][e]) + g_part[2][e]) + g_part[3][e];
        out[idx] = v;
    }
}

// ---------------------------------------------------------------------------
extern "C" void kernel_launch(void* const* d_in, const int* in_sizes, int n_in,
                              void* d_out, int out_size) {
    const float* xc  = (const float*)d_in[0];  // [2,1024,2]
    const float* yc  = (const float*)d_in[1];  // [2,1024,16]
    const float* lsp = (const float*)d_in[3];  // [2]
    float* out = (float*)d_out;

    weights_kernel<<<(M * 2 * G * NC) / 256, 256>>>(xc, lsp);
    compact_kernel<<<(M * NT * NT * 32 + 255) / 256, 256>>>(xc, lsp);
    dim3 g(NT, NT, M * S);
    setconv_partial<<<g, 256>>>(yc);
    finalize_kernel<<<(XTOT + ZTOT + 255) / 256, 256>>>(out);
}

// round 7
// speedup vs baseline: 1.5321x; 1.5321x over previous
#include <cuda_runtime.h>
#include <cstdint>

#define NC 1024
#define DY 16
#define G  256
#define M  2
#define CH 64
#define NT 16          // tiles per dim (G/16)

typedef unsigned long long u64;

// TRANSPOSED axis weights: g_W[axis][m][c][i]  (i contiguous)
__device__ float g_W[2][M][NC][G];           // 4 MB
__device__ int   g_len[M][NT][NT];
__device__ int   g_list[M][NT][NT][NC];      // 2 MB

// ---- packed f32x2 helpers (sm_103a) ----
__device__ __forceinline__ u64 pack2(float lo, float hi) {
    u64 r; asm("mov.b64 %0, {%1, %2};" : "=l"(r) : "f"(lo), "f"(hi)); return r;
}
__device__ __forceinline__ void unpack2(float& lo, float& hi, u64 v) {
    asm("mov.b64 {%0, %1}, %2;" : "=f"(lo), "=f"(hi) : "l"(v));
}
__device__ __forceinline__ void ffma2(u64& d, u64 a, u64 b) {
    asm("fma.rn.f32x2 %0, %1, %2, %0;" : "+l"(d) : "l"(a), "l"(b));
}
__device__ __forceinline__ void lds_v2_u64(u64& a, u64& b, uint32_t addr) {
    asm volatile("ld.shared.v2.b64 {%0, %1}, [%2];" : "=l"(a), "=l"(b) : "r"(addr));
}
__device__ __forceinline__ void cpasync16(uint32_t dst, const void* src, int src_bytes) {
    asm volatile("cp.async.cg.shared.global [%0], [%1], 16, %2;"
                 :: "r"(dst), "l"(src), "r"(src_bytes));
}
__device__ __forceinline__ void cpasync_commit() {
    asm volatile("cp.async.commit_group;");
}
template <int N>
__device__ __forceinline__ void cpasync_wait() {
    asm volatile("cp.async.wait_group %0;" :: "n"(N));
}

// ---------------------------------------------------------------------------
// Kernel 1: build Wx/Wy transposed (1M exps, MUFU path), coalesced stores
// ---------------------------------------------------------------------------
__global__ void weights_kernel(const float* __restrict__ xc,
                               const float* __restrict__ lsp) {
    int idx = blockIdx.x * blockDim.x + threadIdx.x;   // 1,048,576
    int i = idx & (G - 1);
    int c = (idx >> 8) & (NC - 1);
    int d = (idx >> 18) & 1;
    int m = idx >> 19;
    float l = 1e-5f + log1pf(expf(lsp[d]));            // exact softplus
    float rl = 1.0f / l;
    float g = 1.0f + (float)(i - 128) * (1.0f / 64.0f);
    float x = xc[(m * NC + c) * 2 + d];
    float t = (g - x) * rl;
    g_W[d][m][c][i] = __expf(-0.5f * t * t);
}

// ---------------------------------------------------------------------------
// Kernel 2: per-tile c-list compaction (one warp per tile, deterministic)
// ---------------------------------------------------------------------------
__global__ void compact_kernel(const float* __restrict__ xc,
                               const float* __restrict__ lsp) {
    int warp = (blockIdx.x * blockDim.x + threadIdx.x) >> 5;
    int lane = threadIdx.x & 31;
    if (warp >= M * NT * NT) return;
    int jT = warp & (NT - 1);
    int iT = (warp >> 4) & (NT - 1);
    int m  = warp >> 8;

    float rlx = 1.0f / (1e-5f + log1pf(expf(lsp[0])));
    float rly = 1.0f / (1e-5f + log1pf(expf(lsp[1])));
    float x0 = 1.0f + (float)(iT * 16 - 128) * (1.0f / 64.0f);
    float x1 = x0 + 15.0f / 64.0f;
    float y0 = 1.0f + (float)(jT * 16 - 128) * (1.0f / 64.0f);
    float y1 = y0 + 15.0f / 64.0f;
    const float thr = 27.63f;   // weight cutoff ~1e-6

    int count = 0;
    int* lst = g_list[m][iT][jT];
    for (int c0 = 0; c0 < NC; c0 += 32) {
        int c = c0 + lane;
        float cx = xc[(m * NC + c) * 2 + 0];
        float cy = xc[(m * NC + c) * 2 + 1];
        float dx = fmaxf(fmaxf(x0 - cx, cx - x1), 0.0f) * rlx;
        float dy = fmaxf(fmaxf(y0 - cy, cy - y1), 0.0f) * rly;
        bool keep = (dx * dx + dy * dy) <= thr;
        unsigned mask = __ballot_sync(0xffffffffu, keep);
        int off = __popc(mask & ((1u << lane) - 1u));
        if (keep) lst[count + off] = c;
        count += __popc(mask);
    }
    if (lane == 0) g_len[m][iT][jT] = count;
}

// ---------------------------------------------------------------------------
// Kernel 3: fill x_grid_b (first 262,144 floats)
// ---------------------------------------------------------------------------
__global__ void grid_kernel(float* __restrict__ out) {
    int idx = blockIdx.x * blockDim.x + threadIdx.x;
    int d = idx & 1;
    int j = (idx >> 1) & (G - 1);
    int i = (idx >> 9) & (G - 1);
    int v = d ? j : i;
    out[idx] = 1.0f + (float)(v - 128) * (1.0f / 64.0f);
}

// ---------------------------------------------------------------------------
// Kernel 4: fused separable contraction, cp.async double-buffered.
//   z[m,i,j,k] = sum_{c in list} Wx[m,i,c] * Wy[m,j,c] * yc[m,c,k]
// ---------------------------------------------------------------------------
__global__ __launch_bounds__(256, 4)
void setconv_kernel(const float* __restrict__ yc, float* __restrict__ out) {
    __shared__ float  wxs[2][CH][16];   // [buf][c][i] contiguous 16B rows
    __shared__ float  wys[2][CH][16];
    __shared__ float4 ycs[2][CH][4];

    const int m  = blockIdx.z;
    const int iT = blockIdx.y;
    const int jT = blockIdx.x;
    const int tid = threadIdx.x;
    const int ti = tid >> 4;
    const int tj = tid & 15;
    const int iBase = iT * 16;
    const int jBase = jT * 16;

    const int len = g_len[m][iT][jT];
    const int i = iBase + ti, j = jBase + tj;
    float* zo = out + (size_t)(M * G * G * 2) + ((size_t)((m * G + i) * G + j)) * 17;

    if (len == 0) {
#pragma unroll
        for (int k = 0; k < 17; k++) zo[k] = 0.0f;
        return;
    }

    const int* __restrict__ lst = g_list[m][iT][jT];
    const float4* __restrict__ yc4 = (const float4*)yc;

    // staging assignment: cc = tid>>2 (0..63), q = tid&3 (16B quad)
    const int scc = tid >> 2;
    const int sq  = tid & 3;
    const uint32_t wxs_s = (uint32_t)__cvta_generic_to_shared(&wxs[0][0][0]);
    const uint32_t wys_s = (uint32_t)__cvta_generic_to_shared(&wys[0][0][0]);
    const uint32_t ycs_s = (uint32_t)__cvta_generic_to_shared(&ycs[0][0][0]);
    const uint32_t sdoff = (uint32_t)(scc * 16 + sq * 4) * 4;   // byte offset within buf

    const int nchunk = (len + CH - 1) / CH;

    auto stage = [&](int buf, int c0) {
        int cpos = c0 + scc;
        bool valid = cpos < len;
        int cidx = valid ? lst[cpos] : 0;
        int b16 = valid ? 16 : 0;
        uint32_t boff = (uint32_t)buf * (CH * 16 * 4);
        cpasync16(wxs_s + boff + sdoff, &g_W[0][m][cidx][iBase + sq * 4], b16);
        cpasync16(wys_s + boff + sdoff, &g_W[1][m][cidx][jBase + sq * 4], b16);
        cpasync16(ycs_s + boff + sdoff, &yc4[((m * NC + cidx) << 2) + sq], b16);
        cpasync_commit();
    };

    u64 acc2[8];
#pragma unroll
    for (int q = 0; q < 8; q++) acc2[q] = 0ull;
    float accD = 0.0f;

    stage(0, 0);

    for (int t = 0; t < nchunk; t++) {
        int cur = t & 1;
        if (t + 1 < nchunk) {
            stage(cur ^ 1, (t + 1) * CH);
            cpasync_wait<1>();
        } else {
            cpasync_wait<0>();
        }
        __syncthreads();

        const uint32_t wx_a = wxs_s + (uint32_t)cur * (CH * 16 * 4) + (uint32_t)ti * 4;
        const uint32_t wy_a = wys_s + (uint32_t)cur * (CH * 16 * 4) + (uint32_t)tj * 4;
        const uint32_t yc_a = ycs_s + (uint32_t)cur * (CH * 16 * 4);

#pragma unroll 4
        for (int cc = 0; cc < CH; ++cc) {
            float wx, wy;
            asm volatile("ld.shared.f32 %0, [%1];" : "=f"(wx) : "r"(wx_a + cc * 64));
            asm volatile("ld.shared.f32 %0, [%1];" : "=f"(wy) : "r"(wy_a + cc * 64));
            float w = wx * wy;
            accD += w;
            u64 w2 = pack2(w, w);
            u64 y0, y1, y2, y3, y4, y5, y6, y7;
            uint32_t a = yc_a + cc * 64;
            lds_v2_u64(y0, y1, a);
            lds_v2_u64(y2, y3, a + 16);
            lds_v2_u64(y4, y5, a + 32);
            lds_v2_u64(y6, y7, a + 48);
            ffma2(acc2[0], w2, y0);
            ffma2(acc2[1], w2, y1);
            ffma2(acc2[2], w2, y2);
            ffma2(acc2[3], w2, y3);
            ffma2(acc2[4], w2, y4);
            ffma2(acc2[5], w2, y5);
            ffma2(acc2[6], w2, y6);
            ffma2(acc2[7], w2, y7);
        }
        __syncthreads();
    }

    // --- epilogue ---
    float acc[DY];
#pragma unroll
    for (int q = 0; q < 8; q++) unpack2(acc[2 * q], acc[2 * q + 1], acc2[q]);
#pragma unroll
    for (int k = 0; k < DY; k++) zo[k] = acc[k];
    zo[16] = accD;
}

// ---------------------------------------------------------------------------
extern "C" void kernel_launch(void* const* d_in, const int* in_sizes, int n_in,
                              void* d_out, int out_size) {
    const float* xc  = (const float*)d_in[0];  // [2,1024,2]
    const float* yc  = (const float*)d_in[1];  // [2,1024,16]
    const float* lsp = (const float*)d_in[3];  // [2]
    float* out = (float*)d_out;

    weights_kernel<<<(M * 2 * G * NC) / 256, 256>>>(xc, lsp);
    compact_kernel<<<(M * NT * NT * 32 + 255) / 256, 256>>>(xc, lsp);
    grid_kernel<<<(M * G * G * 2) / 256, 256>>>(out);
    dim3 g(NT, NT, M);
    setconv_kernel<<<g, 256>>>(yc, out);
}

// round 8
// speedup vs baseline: 1.5850x; 1.0345x over previous
#include <cuda_runtime.h>
#include <cstdint>

#define NC 1024
#define DY 16
#define G  256
#define M  2
#define CH 64
#define NT 16          // tiles per dim (G/16)

typedef unsigned long long u64;

// TRANSPOSED axis weights: g_W[axis][m][c][i]  (i contiguous)
__device__ float g_W[2][M][NC][G];           // 4 MB
__device__ int   g_len[M][NT][NT];
__device__ int   g_list[M][NT][NT][NC];      // 2 MB

// ---- packed f32x2 helpers (sm_103a) ----
__device__ __forceinline__ u64 pack2(float lo, float hi) {
    u64 r; asm("mov.b64 %0, {%1, %2};" : "=l"(r) : "f"(lo), "f"(hi)); return r;
}
__device__ __forceinline__ void unpack2(float& lo, float& hi, u64 v) {
    asm("mov.b64 {%0, %1}, %2;" : "=f"(lo), "=f"(hi) : "l"(v));
}
__device__ __forceinline__ void ffma2(u64& d, u64 a, u64 b) {
    asm("fma.rn.f32x2 %0, %1, %2, %0;" : "+l"(d) : "l"(a), "l"(b));
}
__device__ __forceinline__ void lds_v2_u64(u64& a, u64& b, uint32_t addr) {
    asm volatile("ld.shared.v2.b64 {%0, %1}, [%2];" : "=l"(a), "=l"(b) : "r"(addr));
}
__device__ __forceinline__ void lds_v2_f32(float& a, float& b, uint32_t addr) {
    asm volatile("ld.shared.v2.f32 {%0, %1}, [%2];" : "=f"(a), "=f"(b) : "r"(addr));
}
__device__ __forceinline__ void cpasync16(uint32_t dst, const void* src, int src_bytes) {
    asm volatile("cp.async.cg.shared.global [%0], [%1], 16, %2;"
                 :: "r"(dst), "l"(src), "r"(src_bytes));
}
__device__ __forceinline__ void cpasync_commit() {
    asm volatile("cp.async.commit_group;");
}
template <int N>
__device__ __forceinline__ void cpasync_wait() {
    asm volatile("cp.async.wait_group %0;" :: "n"(N));
}

// ---------------------------------------------------------------------------
// Kernel 1: build Wx/Wy transposed (1M exps, MUFU), coalesced stores
// ---------------------------------------------------------------------------
__global__ void weights_kernel(const float* __restrict__ xc,
                               const float* __restrict__ lsp) {
    int idx = blockIdx.x * blockDim.x + threadIdx.x;   // 1,048,576
    int i = idx & (G - 1);
    int c = (idx >> 8) & (NC - 1);
    int d = (idx >> 18) & 1;
    int m = idx >> 19;
    float l = 1e-5f + log1pf(expf(lsp[d]));            // exact softplus
    float rl = 1.0f / l;
    float g = 1.0f + (float)(i - 128) * (1.0f / 64.0f);
    float x = xc[(m * NC + c) * 2 + d];
    float t = (g - x) * rl;
    g_W[d][m][c][i] = __expf(-0.5f * t * t);
}

// ---------------------------------------------------------------------------
// Kernel 2: per-tile c-list compaction (one warp per tile, deterministic)
// ---------------------------------------------------------------------------
__global__ void compact_kernel(const float* __restrict__ xc,
                               const float* __restrict__ lsp) {
    int warp = (blockIdx.x * blockDim.x + threadIdx.x) >> 5;
    int lane = threadIdx.x & 31;
    if (warp >= M * NT * NT) return;
    int jT = warp & (NT - 1);
    int iT = (warp >> 4) & (NT - 1);
    int m  = warp >> 8;

    float rlx = 1.0f / (1e-5f + log1pf(expf(lsp[0])));
    float rly = 1.0f / (1e-5f + log1pf(expf(lsp[1])));
    float x0 = 1.0f + (float)(iT * 16 - 128) * (1.0f / 64.0f);
    float x1 = x0 + 15.0f / 64.0f;
    float y0 = 1.0f + (float)(jT * 16 - 128) * (1.0f / 64.0f);
    float y1 = y0 + 15.0f / 64.0f;
    const float thr = 27.63f;   // weight cutoff ~1e-6

    int count = 0;
    int* lst = g_list[m][iT][jT];
    for (int c0 = 0; c0 < NC; c0 += 32) {
        int c = c0 + lane;
        float cx = xc[(m * NC + c) * 2 + 0];
        float cy = xc[(m * NC + c) * 2 + 1];
        float dx = fmaxf(fmaxf(x0 - cx, cx - x1), 0.0f) * rlx;
        float dy = fmaxf(fmaxf(y0 - cy, cy - y1), 0.0f) * rly;
        bool keep = (dx * dx + dy * dy) <= thr;
        unsigned mask = __ballot_sync(0xffffffffu, keep);
        int off = __popc(mask & ((1u << lane) - 1u));
        if (keep) lst[count + off] = c;
        count += __popc(mask);
    }
    if (lane == 0) g_len[m][iT][jT] = count;
}

// ---------------------------------------------------------------------------
// Kernel 3: fill x_grid_b (first 262,144 floats)
// ---------------------------------------------------------------------------
__global__ void grid_kernel(float* __restrict__ out) {
    int idx = blockIdx.x * blockDim.x + threadIdx.x;
    int d = idx & 1;
    int j = (idx >> 1) & (G - 1);
    int i = (idx >> 9) & (G - 1);
    int v = d ? j : i;
    out[idx] = 1.0f + (float)(v - 128) * (1.0f / 64.0f);
}

// ---------------------------------------------------------------------------
// Kernel 4: register-blocked separable contraction, cp.async double-buffered.
// Thread = (2i x 2j x 4k); tid = tk*64 + ti2*8 + tj2.
// k-group 3 (warps 6,7) also accumulates the density channel.
// ---------------------------------------------------------------------------
__global__ __launch_bounds__(256, 4)
void setconv_kernel(const float* __restrict__ yc, float* __restrict__ out) {
    __shared__ float  wxs[2][CH][16];   // [buf][c][i]
    __shared__ float  wys[2][CH][16];   // [buf][c][j]
    __shared__ float4 ycs[2][CH][4];    // [buf][c][k/4]

    const int m  = blockIdx.z;
    const int iT = blockIdx.y;
    const int jT = blockIdx.x;
    const int tid = threadIdx.x;
    const int tj2 = tid & 7;
    const int ti2 = (tid >> 3) & 7;
    const int tk  = tid >> 6;           // 0..3, uniform per warp-pair
    const int iBase = iT * 16;
    const int jBase = jT * 16;

    const int len = g_len[m][iT][jT];
    const int* __restrict__ lst = g_list[m][iT][jT];
    const float4* __restrict__ yc4 = (const float4*)yc;

    // staging: cc = tid>>2, q = tid&3
    const int scc = tid >> 2;
    const int sq  = tid & 3;
    const uint32_t wxs_s = (uint32_t)__cvta_generic_to_shared(&wxs[0][0][0]);
    const uint32_t wys_s = (uint32_t)__cvta_generic_to_shared(&wys[0][0][0]);
    const uint32_t ycs_s = (uint32_t)__cvta_generic_to_shared(&ycs[0][0][0]);
    const uint32_t sdoff = (uint32_t)(scc * 16 + sq * 4) * 4;

    const int nchunk = (len + CH - 1) / CH;

    auto stage = [&](int buf, int c0) {
        int cpos = c0 + scc;
        bool valid = cpos < len;
        int cidx = valid ? lst[cpos] : 0;
        int b16 = valid ? 16 : 0;
        uint32_t boff = (uint32_t)buf * (CH * 16 * 4);
        cpasync16(wxs_s + boff + sdoff, &g_W[0][m][cidx][iBase + sq * 4], b16);
        cpasync16(wys_s + boff + sdoff, &g_W[1][m][cidx][jBase + sq * 4], b16);
        cpasync16(ycs_s + boff + sdoff, &yc4[((m * NC + cidx) << 2) + sq], b16);
        cpasync_commit();
    };

    // accumulators: acc2[ij][p]  ij = di*2+dj, p selects k-pair within group
    u64 acc2[4][2];
#pragma unroll
    for (int a = 0; a < 4; a++) { acc2[a][0] = 0ull; acc2[a][1] = 0ull; }
    float accD[4] = {0.0f, 0.0f, 0.0f, 0.0f};

    if (nchunk > 0) stage(0, 0);

    for (int t = 0; t < nchunk; t++) {
        int cur = t & 1;
        if (t + 1 < nchunk) {
            stage(cur ^ 1, (t + 1) * CH);
            cpasync_wait<1>();
        } else {
            cpasync_wait<0>();
        }
        __syncthreads();

        const uint32_t bo = (uint32_t)cur * (CH * 16 * 4);
        const uint32_t wx_a = wxs_s + bo + (uint32_t)ti2 * 8;
        const uint32_t wy_a = wys_s + bo + (uint32_t)tj2 * 8;
        const uint32_t yc_a = ycs_s + bo + (uint32_t)tk * 16;

        if (tk == 3) {
#pragma unroll 4
            for (int cc = 0; cc < CH; ++cc) {
                float wx0, wx1, wy0, wy1;
                lds_v2_f32(wx0, wx1, wx_a + cc * 64);
                lds_v2_f32(wy0, wy1, wy_a + cc * 64);
                u64 y01, y23;
                asm volatile("ld.shared.v2.b64 {%0, %1}, [%2];"
                             : "=l"(y01), "=l"(y23) : "r"(yc_a + cc * 64));
                float w00 = wx0 * wy0, w01 = wx0 * wy1;
                float w10 = wx1 * wy0, w11 = wx1 * wy1;
                accD[0] += w00; accD[1] += w01; accD[2] += w10; accD[3] += w11;
                u64 p00 = pack2(w00, w00), p01 = pack2(w01, w01);
                u64 p10 = pack2(w10, w10), p11 = pack2(w11, w11);
                ffma2(acc2[0][0], p00, y01); ffma2(acc2[0][1], p00, y23);
                ffma2(acc2[1][0], p01, y01); ffma2(acc2[1][1], p01, y23);
                ffma2(acc2[2][0], p10, y01); ffma2(acc2[2][1], p10, y23);
                ffma2(acc2[3][0], p11, y01); ffma2(acc2[3][1], p11, y23);
            }
        } else {
#pragma unroll 4
            for (int cc = 0; cc < CH; ++cc) {
                float wx0, wx1, wy0, wy1;
                lds_v2_f32(wx0, wx1, wx_a + cc * 64);
                lds_v2_f32(wy0, wy1, wy_a + cc * 64);
                u64 y01, y23;
                asm volatile("ld.shared.v2.b64 {%0, %1}, [%2];"
                             : "=l"(y01), "=l"(y23) : "r"(yc_a + cc * 64));
                float w00 = wx0 * wy0, w01 = wx0 * wy1;
                float w10 = wx1 * wy0, w11 = wx1 * wy1;
                u64 p00 = pack2(w00, w00), p01 = pack2(w01, w01);
                u64 p10 = pack2(w10, w10), p11 = pack2(w11, w11);
                ffma2(acc2[0][0], p00, y01); ffma2(acc2[0][1], p00, y23);
                ffma2(acc2[1][0], p01, y01); ffma2(acc2[1][1], p01, y23);
                ffma2(acc2[2][0], p10, y01); ffma2(acc2[2][1], p10, y23);
                ffma2(acc2[3][0], p11, y01); ffma2(acc2[3][1], p11, y23);
            }
        }
        __syncthreads();
    }

    // --- epilogue: 4 positions x 4 channels (+density for tk==3) ---
    float* outZ = out + (size_t)(M * G * G * 2);
#pragma unroll
    for (int di = 0; di < 2; di++) {
#pragma unroll
        for (int dj = 0; dj < 2; dj++) {
            int ij = di * 2 + dj;
            int i = iBase + ti2 * 2 + di;
            int j = jBase + tj2 * 2 + dj;
            float* zo = outZ + ((size_t)((m * G + i) * G + j)) * 17 + tk * 4;
            float a0, a1, a2, a3;
            unpack2(a0, a1, acc2[ij][0]);
            unpack2(a2, a3, acc2[ij][1]);
            zo[0] = a0; zo[1] = a1; zo[2] = a2; zo[3] = a3;
            if (tk == 3) zo[4] = accD[ij];
        }
    }
}

// ---------------------------------------------------------------------------
extern "C" void kernel_launch(void* const* d_in, const int* in_sizes, int n_in,
                              void* d_out, int out_size) {
    const float* xc  = (const float*)d_in[0];  // [2,1024,2]
    const float* yc  = (const float*)d_in[1];  // [2,1024,16]
    const float* lsp = (const float*)d_in[3];  // [2]
    float* out = (float*)d_out;

    weights_kernel<<<(M * 2 * G * NC) / 256, 256>>>(xc, lsp);
    compact_kernel<<<(M * NT * NT * 32 + 255) / 256, 256>>>(xc, lsp);
    grid_kernel<<<(M * G * G * 2) / 256, 256>>>(out);
    dim3 g(NT, NT, M);
    setconv_kernel<<<g, 256>>>(yc, out);
}

// round 9
// speedup vs baseline: 1.6057x; 1.0131x over previous
#include <cuda_runtime.h>
#include <cstdint>

#define NC 1024
#define DY 16
#define G  256
#define M  2
#define CH 64
#define TS 8           // tile size
#define NT2 32         // tiles per dim (G/TS)
#define XTOT (M * G * G * 2)

typedef unsigned long long u64;

// TRANSPOSED axis weights: g_W[axis][m][c][i]  (i contiguous)
__device__ float g_W[2][M][NC][G];            // 4 MB
__device__ int   g_len[M][NT2][NT2];
__device__ int   g_list[M][NT2][NT2][NC];     // 8 MB

// ---- packed f32x2 helpers ----
__device__ __forceinline__ u64 pack2(float lo, float hi) {
    u64 r; asm("mov.b64 %0, {%1, %2};" : "=l"(r) : "f"(lo), "f"(hi)); return r;
}
__device__ __forceinline__ void unpack2(float& lo, float& hi, u64 v) {
    asm("mov.b64 {%0, %1}, %2;" : "=f"(lo), "=f"(hi) : "l"(v));
}
__device__ __forceinline__ void ffma2(u64& d, u64 a, u64 b) {
    asm("fma.rn.f32x2 %0, %1, %2, %0;" : "+l"(d) : "l"(a), "l"(b));
}
__device__ __forceinline__ void cpasync8(uint32_t dst, const void* src, int src_bytes) {
    asm volatile("cp.async.ca.shared.global [%0], [%1], 8, %2;"
                 :: "r"(dst), "l"(src), "r"(src_bytes));
}
__device__ __forceinline__ void cpasync16(uint32_t dst, const void* src, int src_bytes) {
    asm volatile("cp.async.cg.shared.global [%0], [%1], 16, %2;"
                 :: "r"(dst), "l"(src), "r"(src_bytes));
}
__device__ __forceinline__ void cpasync_commit() {
    asm volatile("cp.async.commit_group;");
}
template <int N>
__device__ __forceinline__ void cpasync_wait() {
    asm volatile("cp.async.wait_group %0;" :: "n"(N));
}

// ---------------------------------------------------------------------------
// Kernel 1: build Wx/Wy transposed (1M exps, MUFU)
// ---------------------------------------------------------------------------
__global__ void weights_kernel(const float* __restrict__ xc,
                               const float* __restrict__ lsp) {
    int idx = blockIdx.x * blockDim.x + threadIdx.x;
    int i = idx & (G - 1);
    int c = (idx >> 8) & (NC - 1);
    int d = (idx >> 18) & 1;
    int m = idx >> 19;
    float l = 1e-5f + log1pf(expf(lsp[d]));
    float rl = 1.0f / l;
    float g = 1.0f + (float)(i - 128) * (1.0f / 64.0f);
    float x = xc[(m * NC + c) * 2 + d];
    float t = (g - x) * rl;
    g_W[d][m][c][i] = __expf(-0.5f * t * t);
}

// ---------------------------------------------------------------------------
// Kernel 2: per-tile c-list compaction (one warp per 8x8 tile, deterministic)
// ---------------------------------------------------------------------------
__global__ void compact_kernel(const float* __restrict__ xc,
                               const float* __restrict__ lsp) {
    int warp = (blockIdx.x * blockDim.x + threadIdx.x) >> 5;
    int lane = threadIdx.x & 31;
    if (warp >= M * NT2 * NT2) return;
    int jT = warp & (NT2 - 1);
    int iT = (warp >> 5) & (NT2 - 1);
    int m  = warp >> 10;

    float rlx = 1.0f / (1e-5f + log1pf(expf(lsp[0])));
    float rly = 1.0f / (1e-5f + log1pf(expf(lsp[1])));
    float x0 = 1.0f + (float)(iT * TS - 128) * (1.0f / 64.0f);
    float x1 = x0 + (float)(TS - 1) / 64.0f;
    float y0 = 1.0f + (float)(jT * TS - 128) * (1.0f / 64.0f);
    float y1 = y0 + (float)(TS - 1) / 64.0f;
    const float thr = 27.63f;   // weight cutoff ~1e-6

    int count = 0;
    int* lst = g_list[m][iT][jT];
    for (int c0 = 0; c0 < NC; c0 += 32) {
        int c = c0 + lane;
        float cx = xc[(m * NC + c) * 2 + 0];
        float cy = xc[(m * NC + c) * 2 + 1];
        float dx = fmaxf(fmaxf(x0 - cx, cx - x1), 0.0f) * rlx;
        float dy = fmaxf(fmaxf(y0 - cy, cy - y1), 0.0f) * rly;
        bool keep = (dx * dx + dy * dy) <= thr;
        unsigned mask = __ballot_sync(0xffffffffu, keep);
        int off = __popc(mask & ((1u << lane) - 1u));
        if (keep) lst[count + off] = c;
        count += __popc(mask);
    }
    if (lane == 0) g_len[m][iT][jT] = count;
}

// ---------------------------------------------------------------------------
// Kernel 3: 8x8-tile contraction, cp.async double-buffered.
// Thread = 1 (i,j) position x 4 channels; tid = tk*64 + ti*8 + tj.
// tk==3 also carries density. Epilogue also writes x_grid for this tile.
// ---------------------------------------------------------------------------
__global__ __launch_bounds__(256, 5)
void setconv_kernel(const float* __restrict__ yc, float* __restrict__ out) {
    __shared__ float  wxs[2][CH][8];    // [buf][c][i]   2 KB
    __shared__ float  wys[2][CH][8];    // [buf][c][j]   2 KB
    __shared__ float4 ycs[2][CH][4];    // [buf][c][k/4] 8 KB

    const int m  = blockIdx.z;
    const int iT = blockIdx.y;
    const int jT = blockIdx.x;
    const int tid = threadIdx.x;
    const int tj = tid & 7;
    const int ti = (tid >> 3) & 7;
    const int tk = tid >> 6;            // 0..3, uniform per warp-pair
    const int iBase = iT * TS;
    const int jBase = jT * TS;
    const int i = iBase + ti, j = jBase + tj;

    // x_grid_b for this tile (always written)
    if (tk == 0) {
        float2 g2;
        g2.x = 1.0f + (float)(i - 128) * (1.0f / 64.0f);
        g2.y = 1.0f + (float)(j - 128) * (1.0f / 64.0f);
        ((float2*)out)[(size_t)(m * G + i) * G + j] = g2;
    }

    const int len = g_len[m][iT][jT];
    float* zo = out + (size_t)XTOT + ((size_t)((m * G + i) * G + j)) * 17 + tk * 4;

    if (len == 0) {
        zo[0] = 0.0f; zo[1] = 0.0f; zo[2] = 0.0f; zo[3] = 0.0f;
        if (tk == 3) zo[4] = 0.0f;
        return;
    }

    const int* __restrict__ lst = g_list[m][iT][jT];
    const float4* __restrict__ yc4 = (const float4*)yc;

    // staging: wx/wy 8B units (cc=tid>>2, h=tid&3), yc 16B (cc=tid>>2, q=tid&3)
    const int scc = tid >> 2;
    const int sh  = tid & 3;
    const uint32_t wxs_s = (uint32_t)__cvta_generic_to_shared(&wxs[0][0][0]);
    const uint32_t wys_s = (uint32_t)__cvta_generic_to_shared(&wys[0][0][0]);
    const uint32_t ycs_s = (uint32_t)__cvta_generic_to_shared(&ycs[0][0][0]);

    const int nchunk = (len + CH - 1) / CH;

    auto stage = [&](int buf, int c0) {
        int cpos = c0 + scc;
        bool valid = cpos < len;
        int cidx = valid ? lst[cpos] : 0;
        int b8  = valid ? 8 : 0;
        int b16 = valid ? 16 : 0;
        uint32_t wboff = (uint32_t)buf * (CH * 8 * 4);
        uint32_t yboff = (uint32_t)buf * (CH * 16 * 4);
        cpasync8 (wxs_s + wboff + (uint32_t)(scc * 32 + sh * 8),
                  &g_W[0][m][cidx][iBase + sh * 2], b8);
        cpasync8 (wys_s + wboff + (uint32_t)(scc * 32 + sh * 8),
                  &g_W[1][m][cidx][jBase + sh * 2], b8);
        cpasync16(ycs_s + yboff + (uint32_t)(scc * 64 + sh * 16),
                  &yc4[((m * NC + cidx) << 2) + sh], b16);
        cpasync_commit();
    };

    u64 acc0 = 0ull, acc1 = 0ull;
    float accD = 0.0f;

    stage(0, 0);

    for (int t = 0; t < nchunk; t++) {
        int cur = t & 1;
        if (t + 1 < nchunk) {
            stage(cur ^ 1, (t + 1) * CH);
            cpasync_wait<1>();
        } else {
            cpasync_wait<0>();
        }
        __syncthreads();

        const uint32_t wx_a = wxs_s + (uint32_t)cur * (CH * 8 * 4) + (uint32_t)ti * 4;
        const uint32_t wy_a = wys_s + (uint32_t)cur * (CH * 8 * 4) + (uint32_t)tj * 4;
        const uint32_t yc_a = ycs_s + (uint32_t)cur * (CH * 16 * 4) + (uint32_t)tk * 16;

        if (tk == 3) {
#pragma unroll 8
            for (int cc = 0; cc < CH; ++cc) {
                float wx, wy;
                asm volatile("ld.shared.f32 %0, [%1];" : "=f"(wx) : "r"(wx_a + cc * 32));
                asm volatile("ld.shared.f32 %0, [%1];" : "=f"(wy) : "r"(wy_a + cc * 32));
                u64 y01, y23;
                asm volatile("ld.shared.v2.b64 {%0, %1}, [%2];"
                             : "=l"(y01), "=l"(y23) : "r"(yc_a + cc * 64));
                float w = wx * wy;
                accD += w;
                u64 p = pack2(w, w);
                ffma2(acc0, p, y01);
                ffma2(acc1, p, y23);
            }
        } else {
#pragma unroll 8
            for (int cc = 0; cc < CH; ++cc) {
                float wx, wy;
                asm volatile("ld.shared.f32 %0, [%1];" : "=f"(wx) : "r"(wx_a + cc * 32));
                asm volatile("ld.shared.f32 %0, [%1];" : "=f"(wy) : "r"(wy_a + cc * 32));
                u64 y01, y23;
                asm volatile("ld.shared.v2.b64 {%0, %1}, [%2];"
                             : "=l"(y01), "=l"(y23) : "r"(yc_a + cc * 64));
                float w = wx * wy;
                u64 p = pack2(w, w);
                ffma2(acc0, p, y01);
                ffma2(acc1, p, y23);
            }
        }
        __syncthreads();
    }

    // --- epilogue ---
    float a0, a1, a2, a3;
    unpack2(a0, a1, acc0);
    unpack2(a2, a3, acc1);
    zo[0] = a0; zo[1] = a1; zo[2] = a2; zo[3] = a3;
    if (tk == 3) zo[4] = accD;
}

// ---------------------------------------------------------------------------
extern "C" void kernel_launch(void* const* d_in, const int* in_sizes, int n_in,
                              void* d_out, int out_size) {
    const float* xc  = (const float*)d_in[0];  // [2,1024,2]
    const float* yc  = (const float*)d_in[1];  // [2,1024,16]
    const float* lsp = (const float*)d_in[3];  // [2]
    float* out = (float*)d_out;

    weights_kernel<<<(M * 2 * G * NC) / 256, 256>>>(xc, lsp);
    compact_kernel<<<(M * NT2 * NT2 * 32) / 256, 256>>>(xc, lsp);
    dim3 g(NT2, NT2, M);
    setconv_kernel<<<g, 256>>>(yc, out);
}